// round 6
// baseline (speedup 1.0000x reference)
#include <cuda_runtime.h>

#define BB 8
#define N1V 50176
#define N2V 12544
#define N3V 3136
#define CNT 100352          // BB*N2V
#define BN_EPS 1e-5f

typedef unsigned long long ull;

// ---------------- scratch ----------------
__device__ float d_xt1[N1V * 24];
__device__ float d_A1[N2V * 81];
__device__ float d_A2[N2V * 81];
__device__ float d_y1[N2V * 256];   // RAW outputs; BN fused into consumers
__device__ float d_y2[N2V * 256];
__device__ float d_y3[N2V * 512];
__device__ float d_stats[256];      // s1[32] q1[32] s2[32] q2[32] s3[64] q3[64]

// ---------------- f32x2 helpers ----------------
__device__ __forceinline__ ull pack2(float lo, float hi) {
    ull r; asm("mov.b64 %0, {%1, %2};" : "=l"(r) : "f"(lo), "f"(hi)); return r;
}
__device__ __forceinline__ void unpack2(ull v, float& lo, float& hi) {
    asm("mov.b64 {%0, %1}, %2;" : "=f"(lo), "=f"(hi) : "l"(v));
}
__device__ __forceinline__ ull ffma2(ull a, ull b, ull c) {
    ull d; asm("fma.rn.f32x2 %0, %1, %2, %3;" : "=l"(d) : "l"(a), "l"(b), "l"(c)); return d;
}

// ---------------- transpose x (8,3,N1) -> xt1[n][24]; block 0 zeros stats ----------------
__global__ void k_transpose(const float* __restrict__ x, float* __restrict__ xt,
                            float* __restrict__ stats) {
    int tid = threadIdx.x;
    if (blockIdx.x == 0) stats[tid] = 0.f;
    int n = blockIdx.x * 256 + tid;
    if (n >= N1V) return;
    float4 t4[6];
    float* t = (float*)t4;
#pragma unroll
    for (int bc = 0; bc < 24; ++bc) t[bc] = x[bc * N1V + n];
    float4* dst = (float4*)(xt + n * 24);
#pragma unroll
    for (int i = 0; i < 6; ++i) dst[i] = t4[i];
}

// ---------------- weight MLP (both offsets, one launch) ----------------
__global__ void __launch_bounds__(128) k_mlp2(const float* __restrict__ off1,
                      const float* __restrict__ off2,
                      const float* __restrict__ Wh, const float* __restrict__ bh,
                      const float* __restrict__ Wo, const float* __restrict__ bo,
                      float* __restrict__ A1, float* __restrict__ A2) {
    __shared__ float sWh[64], sbh[32], sWo[288], sbo[9];
    int tid = threadIdx.x;
    if (tid < 64) sWh[tid] = Wh[tid];
    if (tid < 32) sbh[tid] = bh[tid];
    for (int e = tid; e < 288; e += 128) sWo[e] = Wo[e];
    if (tid < 9) sbo[tid] = bo[tid];
    __syncthreads();
    int id = blockIdx.x * 128 + tid;
    const int T9 = N2V * 9;
    if (id >= 2 * T9) return;
    const float* off = (id < T9) ? off1 : off2;
    float* A = (id < T9) ? A1 : A2;
    int lid = (id < T9) ? id : id - T9;
    float2 o2 = ((const float2*)off)[lid];
    float h[32];
#pragma unroll
    for (int j = 0; j < 32; ++j)
        h[j] = fmaxf(0.f, fmaf(o2.x, sWh[j], fmaf(o2.y, sWh[32 + j], sbh[j])));
#pragma unroll
    for (int t = 0; t < 9; ++t) {
        float acc = sbo[t];
#pragma unroll
        for (int j = 0; j < 32; ++j) acc = fmaf(h[j], sWo[j * 9 + t], acc);
        A[lid * 9 + t] = acc;
    }
}

// ---------------- fused interp-conv layer ----------------
// 256 threads. Generic: P points/group, stage-C tile RT rows x OT cols
// (requires ROWS/RT==32 and O/OT==8). Cross-group A/idx register prefetch.
template <int C, int O, int OT, int RT, int P, int GS, bool BNIN>
__global__ void __launch_bounds__(256) k_layer(
    const float* __restrict__ xin, const float* __restrict__ A,
    const int* __restrict__ nbr, const float* __restrict__ Wg,
    const float* __restrict__ bias, float* __restrict__ yout,
    float* __restrict__ gSum, float* __restrict__ gSq,
    const float* __restrict__ pS, const float* __restrict__ pQ,
    const float* __restrict__ pG, const float* __restrict__ pB)
{
    constexpr int BCin = BB * C;
    constexpr int CT = C * 9;
    constexpr int ROWS = P * BB;
    constexpr int NG = N2V / P;
    constexpr int OTH = OT / 2;
    constexpr int APF = (P * 81 + 255) / 256;

    static_assert(ROWS / RT == 32 && O / OT == 8, "tiling");

    extern __shared__ float sm[];
    float* sm_Wt  = sm;                       // CT*O   [ct*O+o]
    float* sm_G   = sm_Wt + CT * O;           // ROWS*GS
    float* sm_a   = sm_G + ROWS * GS;         // P*108
    float* sm_bias= sm_a + P * 108;           // O
    float* sm_sum = sm_bias + O;              // O
    float* sm_sq  = sm_sum + O;               // O
    float* sm_sc  = sm_sq + O;                // C
    float* sm_sh  = sm_sc + C;                // C
    int*   sm_idx = (int*)(sm_sh + C);        // P*9

    const int tid = threadIdx.x;

    for (int e = tid; e < CT * O; e += 256) {
        int ct = e / O, o = e - ct * O;
        sm_Wt[e] = Wg[o * CT + ct];
    }
    if (tid < O) { sm_bias[tid] = bias[tid]; sm_sum[tid] = 0.f; sm_sq[tid] = 0.f; }
    if (BNIN && tid < C) {
        float mean = pS[tid] * (1.f / CNT);
        float var  = pQ[tid] * (1.f / CNT) - mean * mean;
        float sc   = pG[tid] * rsqrtf(var + BN_EPS);
        sm_sc[tid] = sc;
        sm_sh[tid] = pB[tid] - mean * sc;
    }

    int g = blockIdx.x;
    if (g < NG) {
        if (tid < P * 9) sm_idx[tid] = nbr[g * (P * 9) + tid];
        for (int e = tid; e < P * 81; e += 256) {
            int pt = e / 81, r = e - pt * 81, k = r / 9, t = r - k * 9;
            sm_a[pt * 108 + k * 12 + t] = A[(size_t)g * (P * 81) + e];
        }
    }
    __syncthreads();

    const int bcB = tid & (BCin - 1);
    float scr = 1.f, shr = 0.f;
    if (BNIN) { scr = sm_sc[bcB & (C - 1)]; shr = sm_sh[bcB & (C - 1)]; }

    const int colt = tid & 7;
    const int rowt = tid >> 3;   // 0..31

    float ssum[OT], ssq[OT];
#pragma unroll
    for (int j = 0; j < OT; ++j) { ssum[j] = 0.f; ssq[j] = 0.f; }

    for (; g < NG; g += gridDim.x) {
        const int n0 = g * P;

        // ---- stage B: gather + 9x9 reduce, depth-1 point prefetch ----
        if (C == 32) {
            const int b = bcB >> 5, c = bcB & 31;
            float cur[9], nxt[9];
            {
                const int* ip = sm_idx;
#pragma unroll
                for (int k = 0; k < 9; ++k) cur[k] = xin[ip[k] * BCin + bcB];
            }
#pragma unroll 1
            for (int pt = 0; pt < P; ++pt) {
                if (pt + 1 < P) {
                    const int* ip = sm_idx + (pt + 1) * 9;
#pragma unroll
                    for (int k = 0; k < 9; ++k) nxt[k] = xin[ip[k] * BCin + bcB];
                }
                const float* ap = sm_a + pt * 108;
                ull ac01 = 0, ac23 = 0, ac45 = 0, ac67 = 0; float ac8 = 0.f;
#pragma unroll
                for (int k = 0; k < 9; ++k) {
                    float xv = BNIN ? fmaxf(0.f, fmaf(cur[k], scr, shr)) : cur[k];
                    ull xx = pack2(xv, xv);
                    const ulonglong2* a2 = (const ulonglong2*)(ap + k * 12);
                    ulonglong2 a03 = a2[0], a47 = a2[1];
                    ac01 = ffma2(xx, a03.x, ac01);
                    ac23 = ffma2(xx, a03.y, ac23);
                    ac45 = ffma2(xx, a47.x, ac45);
                    ac67 = ffma2(xx, a47.y, ac67);
                    ac8 = fmaf(xv, ap[k * 12 + 8], ac8);
                }
                float* gp = sm_G + (pt * 8 + b) * GS + c * 9;
                unpack2(ac01, gp[0], gp[1]);
                unpack2(ac23, gp[2], gp[3]);
                unpack2(ac45, gp[4], gp[5]);
                unpack2(ac67, gp[6], gp[7]);
                gp[8] = ac8;
#pragma unroll
                for (int k = 0; k < 9; ++k) cur[k] = nxt[k];
            }
        } else {  // C == 3
#pragma unroll
            for (int it = tid; it < P * 24; it += 256) {
                const int pt = it / 24, bc = it - pt * 24;
                const int b = bc / 3, c = bc - b * 3;
                const float* ap = sm_a + pt * 108;
                const int* ip = sm_idx + pt * 9;
                float xr[9];
#pragma unroll
                for (int k = 0; k < 9; ++k) xr[k] = xin[ip[k] * BCin + bc];
                ull ac01 = 0, ac23 = 0, ac45 = 0, ac67 = 0; float ac8 = 0.f;
#pragma unroll
                for (int k = 0; k < 9; ++k) {
                    ull xx = pack2(xr[k], xr[k]);
                    const ulonglong2* a2 = (const ulonglong2*)(ap + k * 12);
                    ulonglong2 a03 = a2[0], a47 = a2[1];
                    ac01 = ffma2(xx, a03.x, ac01);
                    ac23 = ffma2(xx, a03.y, ac23);
                    ac45 = ffma2(xx, a47.x, ac45);
                    ac67 = ffma2(xx, a47.y, ac67);
                    ac8 = fmaf(xr[k], ap[k * 12 + 8], ac8);
                }
                float* gp = sm_G + (pt * 8 + b) * GS + c * 9;
                unpack2(ac01, gp[0], gp[1]);
                unpack2(ac23, gp[2], gp[3]);
                unpack2(ac45, gp[4], gp[5]);
                unpack2(ac67, gp[6], gp[7]);
                gp[8] = ac8;
            }
        }
        __syncthreads();   // G ready; sm_a / sm_idx consumed

        // ---- register-prefetch next group's A + idx (hidden under stage C) ----
        const int gn = g + gridDim.x;
        const bool havenext = (gn < NG);
        float apre[APF]; int ipre = 0;
        if (havenext) {
#pragma unroll
            for (int i = 0; i < APF; ++i) {
                int e = tid + i * 256;
                if (e < P * 81) apre[i] = A[(size_t)gn * (P * 81) + e];
            }
            if (tid < P * 9) ipre = nbr[gn * (P * 9) + tid];
        }

        // ---- stage C: RT rows x OT cols per thread ----
        {
            const float* Gp = sm_G + (rowt * RT) * GS;
            ull bini[OTH];
#pragma unroll
            for (int j = 0; j < OTH; ++j)
                bini[j] = pack2(sm_bias[colt * OT + 2 * j], sm_bias[colt * OT + 2 * j + 1]);
            ull acc[RT][OTH];
#pragma unroll
            for (int i = 0; i < RT; ++i)
#pragma unroll
                for (int j = 0; j < OTH; ++j) acc[i][j] = bini[j];

#pragma unroll 4
            for (int ct = 0; ct < CT; ++ct) {
                ull w[OTH];
                if (OT == 8) {
                    const ulonglong2* wp = (const ulonglong2*)(sm_Wt + ct * O + colt * 8);
                    ulonglong2 wA = wp[0], wB = wp[1];
                    w[0] = wA.x; w[1] = wA.y;
                    if (OTH > 2) { w[2] = wB.x; w[3] = wB.y; }
                } else {
                    ulonglong2 wA = *(const ulonglong2*)(sm_Wt + ct * O + colt * 4);
                    w[0] = wA.x; w[1] = wA.y;
                }
#pragma unroll
                for (int i = 0; i < RT; ++i) {
                    float gv = Gp[i * GS + ct];
                    ull gg = pack2(gv, gv);
#pragma unroll
                    for (int j = 0; j < OTH; ++j)
                        acc[i][j] = ffma2(gg, w[j], acc[i][j]);
                }
            }

#pragma unroll
            for (int i = 0; i < RT; ++i) {
                int row = rowt * RT + i, pt = row >> 3, b = row & 7;
                float* yp = yout + (size_t)(n0 + pt) * (BB * O) + b * O + colt * OT;
                float v[OT];
#pragma unroll
                for (int j = 0; j < OTH; ++j) unpack2(acc[i][j], v[2 * j], v[2 * j + 1]);
#pragma unroll
                for (int q = 0; q < OT / 4; ++q)
                    ((float4*)yp)[q] = make_float4(v[4 * q], v[4 * q + 1], v[4 * q + 2], v[4 * q + 3]);
#pragma unroll
                for (int j = 0; j < OT; ++j) {
                    ssum[j] += v[j];
                    ssq[j] = fmaf(v[j], v[j], ssq[j]);
                }
            }
        }
        __syncthreads();   // G consumed; sm_a safe to overwrite

        if (havenext) {
#pragma unroll
            for (int i = 0; i < APF; ++i) {
                int e = tid + i * 256;
                if (e < P * 81) {
                    int pt = e / 81, r = e - pt * 81, k = r / 9, t = r - k * 9;
                    sm_a[pt * 108 + k * 12 + t] = apre[i];
                }
            }
            if (tid < P * 9) sm_idx[tid] = ipre;
            __syncthreads();
        }
    }

#pragma unroll
    for (int j = 0; j < OT; ++j) {
        atomicAdd(sm_sum + colt * OT + j, ssum[j]);
        atomicAdd(sm_sq  + colt * OT + j, ssq[j]);
    }
    __syncthreads();
    if (tid < O) {
        atomicAdd(gSum + tid, sm_sum[tid]);
        atomicAdd(gSq  + tid, sm_sq[tid]);
    }
}

// ---------------- max pool (+BN3+ReLU) + transpose to (8,64,N3) ----------------
__global__ void k_pool(const float* __restrict__ x3, const int* __restrict__ pidx,
                       float* __restrict__ out,
                       const float* __restrict__ gS, const float* __restrict__ gQ,
                       const float* __restrict__ gamma, const float* __restrict__ beta) {
    __shared__ float smp[16 * 513];
    int tid = threadIdx.x;
    int base = blockIdx.x * 16;
    int o = tid & 63;
    float mean = gS[o] * (1.f / CNT);
    float var  = gQ[o] * (1.f / CNT) - mean * mean;
    float sc   = gamma[o] * rsqrtf(var + BN_EPS);
    float sh   = beta[o] - mean * sc;
    bool pos = (sc >= 0.f);
    float init = pos ? -3.4e38f : 3.4e38f;
    for (int i = 0; i < 16; ++i) {
        int n3 = base + i;
        float m0 = init, m1 = init;
#pragma unroll
        for (int k = 0; k < 9; ++k) {
            const float* row = x3 + (size_t)pidx[n3 * 9 + k] * 512;
            float r0 = row[tid], r1 = row[tid + 256];
            if (pos) { m0 = fmaxf(m0, r0); m1 = fmaxf(m1, r1); }
            else     { m0 = fminf(m0, r0); m1 = fminf(m1, r1); }
        }
        smp[i * 513 + tid]       = fmaxf(0.f, fmaf(m0, sc, sh));
        smp[i * 513 + tid + 256] = fmaxf(0.f, fmaf(m1, sc, sh));
    }
    __syncthreads();
#pragma unroll
    for (int h = 0; h < 2; ++h) {
        int bc = tid + h * 256;
        float4 t4[4];
        float* t = (float*)t4;
#pragma unroll
        for (int i = 0; i < 16; ++i) t[i] = smp[i * 513 + bc];
        float4* dst = (float4*)(out + (size_t)bc * N3V + base);
#pragma unroll
        for (int q = 0; q < 4; ++q) dst[q] = t4[q];
    }
}

static constexpr size_t layer_smem(int C, int O, int GS, int P) {
    return (size_t)4 * (C * 9 * O + P * 8 * GS + P * 108 + 3 * O + 2 * C + P * 9);
}

extern "C" void kernel_launch(void* const* d_in, const int* in_sizes, int n_in,
                              void* d_out, int out_size) {
    const float* x    = (const float*)d_in[0];
    const int*   nbr1 = (const int*)d_in[1];
    const float* off1 = (const float*)d_in[2];
    const int*   nbr2 = (const int*)d_in[3];
    const float* off2 = (const float*)d_in[4];
    const int*   pidx = (const int*)d_in[5];
    const float* Wh   = (const float*)d_in[6];
    const float* bh   = (const float*)d_in[7];
    const float* Wo   = (const float*)d_in[8];
    const float* bo   = (const float*)d_in[9];
    const float* W1   = (const float*)d_in[10];
    const float* b1   = (const float*)d_in[11];
    const float* W2   = (const float*)d_in[12];
    const float* b2   = (const float*)d_in[13];
    const float* W3   = (const float*)d_in[14];
    const float* b3   = (const float*)d_in[15];
    const float* g1   = (const float*)d_in[16];
    const float* be1  = (const float*)d_in[17];
    const float* g2   = (const float*)d_in[18];
    const float* be2  = (const float*)d_in[19];
    const float* g3   = (const float*)d_in[20];
    const float* be3  = (const float*)d_in[21];
    float* out = (float*)d_out;

    float *xt1, *A1, *A2, *y1, *y2, *y3, *stats;
    cudaGetSymbolAddress((void**)&xt1, d_xt1);
    cudaGetSymbolAddress((void**)&A1, d_A1);
    cudaGetSymbolAddress((void**)&A2, d_A2);
    cudaGetSymbolAddress((void**)&y1, d_y1);
    cudaGetSymbolAddress((void**)&y2, d_y2);
    cudaGetSymbolAddress((void**)&y3, d_y3);
    cudaGetSymbolAddress((void**)&stats, d_stats);

    const size_t sm1 = layer_smem(3, 32, 29, 16);
    const size_t sm2 = layer_smem(32, 32, 289, 8);
    const size_t sm3 = layer_smem(32, 64, 289, 4);
    cudaFuncSetAttribute((const void*)k_layer<3, 32, 4, 4, 16, 29, false>,  cudaFuncAttributeMaxDynamicSharedMemorySize, (int)sm1);
    cudaFuncSetAttribute((const void*)k_layer<32, 32, 4, 2, 8, 289, true>,  cudaFuncAttributeMaxDynamicSharedMemorySize, (int)sm2);
    cudaFuncSetAttribute((const void*)k_layer<32, 64, 8, 1, 4, 289, true>,  cudaFuncAttributeMaxDynamicSharedMemorySize, (int)sm3);

    k_transpose<<<(N1V + 255) / 256, 256>>>(x, xt1, stats);
    k_mlp2<<<(2 * N2V * 9 + 127) / 128, 128>>>(off1, off2, Wh, bh, Wo, bo, A1, A2);

    // layer1: one group per CTA
    k_layer<3, 32, 4, 4, 16, 29, false><<<784, 256, sm1>>>(
        xt1, A1, nbr1, W1, b1, y1, stats + 0, stats + 32,
        nullptr, nullptr, nullptr, nullptr);
    // layer2: P=8 -> 2 CTAs/SM
    k_layer<32, 32, 4, 2, 8, 289, true><<<296, 256, sm2>>>(
        y1, A2, nbr2, W2, b2, y2, stats + 64, stats + 96,
        stats + 0, stats + 32, g1, be1);
    // layer3: P=4 -> 2 CTAs/SM
    k_layer<32, 64, 8, 1, 4, 289, true><<<296, 256, sm3>>>(
        y2, A2, nbr2, W3, b3, y3, stats + 128, stats + 192,
        stats + 64, stats + 96, g2, be2);

    k_pool<<<N3V / 16, 256>>>(y3, pidx, out, stats + 128, stats + 192, g3, be3);
}

// round 8
// speedup vs baseline: 1.9128x; 1.9128x over previous
#include <cuda_runtime.h>

#define BB 8
#define N1V 50176
#define N2V 12544
#define N3V 3136
#define CNT 100352          // BB*N2V
#define BN_EPS 1e-5f

typedef unsigned long long ull;

// ---------------- scratch ----------------
__device__ float d_xt1[N1V * 24];
__device__ float d_A1[N2V * 81];
__device__ float d_A2[N2V * 81];
__device__ float d_y1[N2V * 256];   // RAW outputs; BN fused into consumers
__device__ float d_y2[N2V * 256];
__device__ float d_y3[N2V * 512];
__device__ float d_stats[256];      // s1[32] q1[32] s2[32] q2[32] s3[64] q3[64]

// ---------------- f32x2 helpers ----------------
__device__ __forceinline__ ull pack2(float lo, float hi) {
    ull r; asm("mov.b64 %0, {%1, %2};" : "=l"(r) : "f"(lo), "f"(hi)); return r;
}
__device__ __forceinline__ void unpack2(ull v, float& lo, float& hi) {
    asm("mov.b64 {%0, %1}, %2;" : "=f"(lo), "=f"(hi) : "l"(v));
}
__device__ __forceinline__ ull ffma2(ull a, ull b, ull c) {
    ull d; asm("fma.rn.f32x2 %0, %1, %2, %3;" : "=l"(d) : "l"(a), "l"(b), "l"(c)); return d;
}

// ---------------- transpose x (8,3,N1) -> xt1[n][24]; block 0 zeros stats ----------------
__global__ void k_transpose(const float* __restrict__ x, float* __restrict__ xt,
                            float* __restrict__ stats) {
    int tid = threadIdx.x;
    if (blockIdx.x == 0) stats[tid] = 0.f;
    int n = blockIdx.x * 256 + tid;
    if (n >= N1V) return;
    float4 t4[6];
    float* t = (float*)t4;
#pragma unroll
    for (int bc = 0; bc < 24; ++bc) t[bc] = x[bc * N1V + n];
    float4* dst = (float4*)(xt + n * 24);
#pragma unroll
    for (int i = 0; i < 6; ++i) dst[i] = t4[i];
}

// ---------------- weight MLP (both offsets, one launch) ----------------
__global__ void __launch_bounds__(128) k_mlp2(const float* __restrict__ off1,
                      const float* __restrict__ off2,
                      const float* __restrict__ Wh, const float* __restrict__ bh,
                      const float* __restrict__ Wo, const float* __restrict__ bo,
                      float* __restrict__ A1, float* __restrict__ A2) {
    __shared__ float sWh[64], sbh[32], sWo[288], sbo[9];
    int tid = threadIdx.x;
    if (tid < 64) sWh[tid] = Wh[tid];
    if (tid < 32) sbh[tid] = bh[tid];
    for (int e = tid; e < 288; e += 128) sWo[e] = Wo[e];
    if (tid < 9) sbo[tid] = bo[tid];
    __syncthreads();
    int id = blockIdx.x * 128 + tid;
    const int T9 = N2V * 9;
    if (id >= 2 * T9) return;
    const float* off = (id < T9) ? off1 : off2;
    float* A = (id < T9) ? A1 : A2;
    int lid = (id < T9) ? id : id - T9;
    float2 o2 = ((const float2*)off)[lid];
    float h[32];
#pragma unroll
    for (int j = 0; j < 32; ++j)
        h[j] = fmaxf(0.f, fmaf(o2.x, sWh[j], fmaf(o2.y, sWh[32 + j], sbh[j])));
#pragma unroll
    for (int t = 0; t < 9; ++t) {
        float acc = sbo[t];
#pragma unroll
        for (int j = 0; j < 32; ++j) acc = fmaf(h[j], sWo[j * 9 + t], acc);
        A[lid * 9 + t] = acc;
    }
}

// ---------------- fused interp-conv layer, ct-split passes ----------------
// G stored TRANSPOSED: sm_G[ct_local * 132 + row], row = pt*8+b, rows = 128.
// NQ ct-passes per group; stage-C accumulators persist in registers across passes.
template <int C, int O, int OT, int RT, int P, int NQ, bool BNIN>
__global__ void __launch_bounds__(256) k_layer(
    const float* __restrict__ xin, const float* __restrict__ A,
    const int* __restrict__ nbr, const float* __restrict__ Wg,
    const float* __restrict__ bias, float* __restrict__ yout,
    float* __restrict__ gSum, float* __restrict__ gSq,
    const float* __restrict__ pS, const float* __restrict__ pQ,
    const float* __restrict__ pG, const float* __restrict__ pB)
{
    constexpr int BCin = BB * C;
    constexpr int CT = C * 9;
    constexpr int CQ = C / NQ;         // channels per pass
    constexpr int CTQ = CQ * 9;        // ct per pass
    constexpr int ROWS = P * BB;       // 128
    constexpr int NG = N2V / P;        // 784
    constexpr int OTH = OT / 2;
    constexpr int RS = 132;            // G row-stride (ct-major)
    constexpr int WS = (O == 64) ? 72 : O;   // W stride (swizzled for O=64)
    constexpr int BCq = BB * CQ;       // thread slots per point per pass
    constexpr int PPASS = 256 / BCq;   // points in flight per pass
    constexpr int NIT = P / PPASS;

    static_assert(ROWS / RT == 32 && O / OT == 8, "tiling");

    extern __shared__ float sm[];
    float* sm_Wt  = sm;                       // CT*WS
    float* sm_G   = sm_Wt + CT * WS;          // CTQ*RS
    float* sm_a   = sm_G + CTQ * RS;          // P*108
    float* sm_bias= sm_a + P * 108;           // O
    float* sm_sum = sm_bias + O;              // O
    float* sm_sq  = sm_sum + O;               // O
    float* sm_sc  = sm_sq + O;                // C
    float* sm_sh  = sm_sc + C;                // C
    int*   sm_idx = (int*)(sm_sh + C);        // P*9

    const int tid = threadIdx.x;

    // one-time: weight transpose (+swizzle for O=64), bias, stats, BN coeffs
    for (int e = tid; e < CT * O; e += 256) {
        int ct = e / O, o = e - ct * O;
        int op = (O == 64 && o >= 32) ? o + 4 : o;
        sm_Wt[ct * WS + op] = Wg[o * CT + ct];
    }
    if (tid < O) { sm_bias[tid] = bias[tid]; sm_sum[tid] = 0.f; sm_sq[tid] = 0.f; }
    if (BNIN && tid < C) {
        float mean = pS[tid] * (1.f / CNT);
        float var  = pQ[tid] * (1.f / CNT) - mean * mean;
        float sc   = pG[tid] * rsqrtf(var + BN_EPS);
        sm_sc[tid] = sc;
        sm_sh[tid] = pB[tid] - mean * sc;
    }

    // stage-B decode (C==32 path)
    const int ptofs = tid / BCq;
    const int rem   = tid - ptofs * BCq;
    const int bB    = rem / CQ;
    const int ciB   = rem - bB * CQ;

    // stage-C decode
    const int colt = tid & 7;
    const int rowt = tid >> 3;   // 0..31
    const int woff = (O == 64) ? (colt * 8 + (colt >> 2) * 4) : (colt * OT);

    float ssum[OT], ssq[OT];
#pragma unroll
    for (int j = 0; j < OT; ++j) { ssum[j] = 0.f; ssq[j] = 0.f; }

    for (int g = blockIdx.x; g < NG; g += gridDim.x) {
        const int n0 = g * P;
        if (tid < P * 9) sm_idx[tid] = nbr[n0 * 9 + tid];
        for (int e = tid; e < P * 81; e += 256) {
            int pt = e / 81, r = e - pt * 81, k = r / 9, t = r - k * 9;
            sm_a[pt * 108 + k * 12 + t] = A[(size_t)n0 * 81 + e];
        }
        __syncthreads();

        // persistent stage-C accumulators
        ull acc[RT][OTH];
#pragma unroll
        for (int i = 0; i < RT; ++i)
#pragma unroll
            for (int j = 0; j < OTH; ++j)
                acc[i][j] = pack2(sm_bias[colt * OT + 2 * j], sm_bias[colt * OT + 2 * j + 1]);

#pragma unroll 1
        for (int q = 0; q < NQ; ++q) {
            // ---- stage B pass q: compute G slice (transposed) ----
            if (C == 32) {
                const int cbase = q * CQ;
                const int colg = bB * C + cbase + ciB;     // b*C + c  (FIXED)
                float scq = 1.f, shq = 0.f;
                if (BNIN) { scq = sm_sc[cbase + ciB]; shq = sm_sh[cbase + ciB]; }
#pragma unroll 1
                for (int it = 0; it < NIT; ++it) {
                    const int pt = it * PPASS + ptofs;
                    const int* ip = sm_idx + pt * 9;
                    float xr[9];
#pragma unroll
                    for (int k = 0; k < 9; ++k) xr[k] = xin[ip[k] * BCin + colg];
                    if (BNIN) {
#pragma unroll
                        for (int k = 0; k < 9; ++k) xr[k] = fmaxf(0.f, fmaf(xr[k], scq, shq));
                    }
                    const float* ap = sm_a + pt * 108;
                    ull ac01 = 0, ac23 = 0, ac45 = 0, ac67 = 0; float ac8 = 0.f;
#pragma unroll
                    for (int k = 0; k < 9; ++k) {
                        ull xx = pack2(xr[k], xr[k]);
                        const ulonglong2* a2 = (const ulonglong2*)(ap + k * 12);
                        ulonglong2 a03 = a2[0], a47 = a2[1];
                        ac01 = ffma2(xx, a03.x, ac01);
                        ac23 = ffma2(xx, a03.y, ac23);
                        ac45 = ffma2(xx, a47.x, ac45);
                        ac67 = ffma2(xx, a47.y, ac67);
                        ac8 = fmaf(xr[k], ap[k * 12 + 8], ac8);
                    }
                    float* gp = sm_G + (ciB * 9) * RS + pt * 8 + bB;
                    float v0,v1,v2,v3,v4,v5,v6,v7;
                    unpack2(ac01, v0, v1); unpack2(ac23, v2, v3);
                    unpack2(ac45, v4, v5); unpack2(ac67, v6, v7);
                    gp[0*RS]=v0; gp[1*RS]=v1; gp[2*RS]=v2; gp[3*RS]=v3;
                    gp[4*RS]=v4; gp[5*RS]=v5; gp[6*RS]=v6; gp[7*RS]=v7;
                    gp[8*RS]=ac8;
                }
            } else {  // C == 3, NQ == 1
#pragma unroll
                for (int it = tid; it < P * 24; it += 256) {
                    const int pt = it / 24, bc = it - pt * 24;
                    const int b = bc / 3, c = bc - b * 3;
                    const float* ap = sm_a + pt * 108;
                    const int* ip = sm_idx + pt * 9;
                    float xr[9];
#pragma unroll
                    for (int k = 0; k < 9; ++k) xr[k] = xin[ip[k] * BCin + bc];
                    ull ac01 = 0, ac23 = 0, ac45 = 0, ac67 = 0; float ac8 = 0.f;
#pragma unroll
                    for (int k = 0; k < 9; ++k) {
                        ull xx = pack2(xr[k], xr[k]);
                        const ulonglong2* a2 = (const ulonglong2*)(ap + k * 12);
                        ulonglong2 a03 = a2[0], a47 = a2[1];
                        ac01 = ffma2(xx, a03.x, ac01);
                        ac23 = ffma2(xx, a03.y, ac23);
                        ac45 = ffma2(xx, a47.x, ac45);
                        ac67 = ffma2(xx, a47.y, ac67);
                        ac8 = fmaf(xr[k], ap[k * 12 + 8], ac8);
                    }
                    float* gp = sm_G + (c * 9) * RS + pt * 8 + b;
                    float v0,v1,v2,v3,v4,v5,v6,v7;
                    unpack2(ac01, v0, v1); unpack2(ac23, v2, v3);
                    unpack2(ac45, v4, v5); unpack2(ac67, v6, v7);
                    gp[0*RS]=v0; gp[1*RS]=v1; gp[2*RS]=v2; gp[3*RS]=v3;
                    gp[4*RS]=v4; gp[5*RS]=v5; gp[6*RS]=v6; gp[7*RS]=v7;
                    gp[8*RS]=ac8;
                }
            }
            __syncthreads();   // G slice ready

            // ---- stage C pass q: accumulate over this ct slice ----
            {
                const float* Wq = sm_Wt + (q * CTQ) * WS + woff;
                const float* Gq = sm_G + rowt * RT;
#pragma unroll 4
                for (int ctl = 0; ctl < CTQ; ++ctl) {
                    ull w[OTH];
                    {
                        ulonglong2 wA = *(const ulonglong2*)(Wq + ctl * WS);
                        w[0] = wA.x; w[1] = wA.y;
                        if (OTH > 2) {
                            ulonglong2 wB = *(const ulonglong2*)(Wq + ctl * WS + 4);
                            w[2] = wB.x; w[3] = wB.y;
                        }
                    }
                    float4 gv = *(const float4*)(Gq + ctl * RS);
                    ull gg0 = pack2(gv.x, gv.x), gg1 = pack2(gv.y, gv.y);
                    ull gg2 = pack2(gv.z, gv.z), gg3 = pack2(gv.w, gv.w);
#pragma unroll
                    for (int j = 0; j < OTH; ++j) {
                        acc[0][j] = ffma2(gg0, w[j], acc[0][j]);
                        acc[1][j] = ffma2(gg1, w[j], acc[1][j]);
                        acc[2][j] = ffma2(gg2, w[j], acc[2][j]);
                        acc[3][j] = ffma2(gg3, w[j], acc[3][j]);
                    }
                }
            }
            __syncthreads();   // G slice consumed; safe to overwrite
        }

        // ---- write out + stats (registers only) ----
#pragma unroll
        for (int i = 0; i < RT; ++i) {
            int row = rowt * RT + i, pt = row >> 3, b = row & 7;
            float* yp = yout + (size_t)(n0 + pt) * (BB * O) + b * O + colt * OT;
            float v[OT];
#pragma unroll
            for (int j = 0; j < OTH; ++j) unpack2(acc[i][j], v[2 * j], v[2 * j + 1]);
#pragma unroll
            for (int qv = 0; qv < OT / 4; ++qv)
                ((float4*)yp)[qv] = make_float4(v[4 * qv], v[4 * qv + 1], v[4 * qv + 2], v[4 * qv + 3]);
#pragma unroll
            for (int j = 0; j < OT; ++j) {
                ssum[j] += v[j];
                ssq[j] = fmaf(v[j], v[j], ssq[j]);
            }
        }
    }

    // stats merge: regs -> smem -> global
#pragma unroll
    for (int j = 0; j < OT; ++j) {
        atomicAdd(sm_sum + colt * OT + j, ssum[j]);
        atomicAdd(sm_sq  + colt * OT + j, ssq[j]);
    }
    __syncthreads();
    if (tid < O) {
        atomicAdd(gSum + tid, sm_sum[tid]);
        atomicAdd(gSq  + tid, sm_sq[tid]);
    }
}

// ---------------- max pool (+BN3+ReLU) + transpose to (8,64,N3) ----------------
__global__ void k_pool(const float* __restrict__ x3, const int* __restrict__ pidx,
                       float* __restrict__ out,
                       const float* __restrict__ gS, const float* __restrict__ gQ,
                       const float* __restrict__ gamma, const float* __restrict__ beta) {
    __shared__ float smp[16 * 513];
    int tid = threadIdx.x;
    int base = blockIdx.x * 16;
    int o = tid & 63;
    float mean = gS[o] * (1.f / CNT);
    float var  = gQ[o] * (1.f / CNT) - mean * mean;
    float sc   = gamma[o] * rsqrtf(var + BN_EPS);
    float sh   = beta[o] - mean * sc;
    bool pos = (sc >= 0.f);
    float init = pos ? -3.4e38f : 3.4e38f;
    for (int i = 0; i < 16; ++i) {
        int n3 = base + i;
        float m0 = init, m1 = init;
#pragma unroll
        for (int k = 0; k < 9; ++k) {
            const float* row = x3 + (size_t)pidx[n3 * 9 + k] * 512;
            float r0 = row[tid], r1 = row[tid + 256];
            if (pos) { m0 = fmaxf(m0, r0); m1 = fmaxf(m1, r1); }
            else     { m0 = fminf(m0, r0); m1 = fminf(m1, r1); }
        }
        smp[i * 513 + tid]       = fmaxf(0.f, fmaf(m0, sc, sh));
        smp[i * 513 + tid + 256] = fmaxf(0.f, fmaf(m1, sc, sh));
    }
    __syncthreads();
#pragma unroll
    for (int h = 0; h < 2; ++h) {
        int bc = tid + h * 256;
        float4 t4[4];
        float* t = (float*)t4;
#pragma unroll
        for (int i = 0; i < 16; ++i) t[i] = smp[i * 513 + bc];
        float4* dst = (float4*)(out + (size_t)bc * N3V + base);
#pragma unroll
        for (int q = 0; q < 4; ++q) dst[q] = t4[q];
    }
}

static constexpr size_t layer_smem(int C, int O, int NQ) {
    int CT = C * 9;
    int WS = (O == 64) ? 72 : O;
    int CTQ = (C / NQ) * 9;
    return (size_t)4 * (CT * WS + CTQ * 132 + 16 * 108 + 3 * O + 2 * C + 144);
}

extern "C" void kernel_launch(void* const* d_in, const int* in_sizes, int n_in,
                              void* d_out, int out_size) {
    const float* x    = (const float*)d_in[0];
    const int*   nbr1 = (const int*)d_in[1];
    const float* off1 = (const float*)d_in[2];
    const int*   nbr2 = (const int*)d_in[3];
    const float* off2 = (const float*)d_in[4];
    const int*   pidx = (const int*)d_in[5];
    const float* Wh   = (const float*)d_in[6];
    const float* bh   = (const float*)d_in[7];
    const float* Wo   = (const float*)d_in[8];
    const float* bo   = (const float*)d_in[9];
    const float* W1   = (const float*)d_in[10];
    const float* b1   = (const float*)d_in[11];
    const float* W2   = (const float*)d_in[12];
    const float* b2   = (const float*)d_in[13];
    const float* W3   = (const float*)d_in[14];
    const float* b3   = (const float*)d_in[15];
    const float* g1   = (const float*)d_in[16];
    const float* be1  = (const float*)d_in[17];
    const float* g2   = (const float*)d_in[18];
    const float* be2  = (const float*)d_in[19];
    const float* g3   = (const float*)d_in[20];
    const float* be3  = (const float*)d_in[21];
    float* out = (float*)d_out;

    float *xt1, *A1, *A2, *y1, *y2, *y3, *stats;
    cudaGetSymbolAddress((void**)&xt1, d_xt1);
    cudaGetSymbolAddress((void**)&A1, d_A1);
    cudaGetSymbolAddress((void**)&A2, d_A2);
    cudaGetSymbolAddress((void**)&y1, d_y1);
    cudaGetSymbolAddress((void**)&y2, d_y2);
    cudaGetSymbolAddress((void**)&y3, d_y3);
    cudaGetSymbolAddress((void**)&stats, d_stats);

    const size_t sm1 = layer_smem(3, 32, 1);
    const size_t sm2 = layer_smem(32, 32, 4);
    const size_t sm3 = layer_smem(32, 64, 8);
    cudaFuncSetAttribute((const void*)k_layer<3, 32, 4, 4, 16, 1, false>, cudaFuncAttributeMaxDynamicSharedMemorySize, (int)sm1);
    cudaFuncSetAttribute((const void*)k_layer<32, 32, 4, 4, 16, 4, true>, cudaFuncAttributeMaxDynamicSharedMemorySize, (int)sm2);
    cudaFuncSetAttribute((const void*)k_layer<32, 64, 8, 4, 16, 8, true>, cudaFuncAttributeMaxDynamicSharedMemorySize, (int)sm3);

    k_transpose<<<(N1V + 255) / 256, 256>>>(x, xt1, stats);
    k_mlp2<<<(2 * N2V * 9 + 127) / 128, 128>>>(off1, off2, Wh, bh, Wo, bo, A1, A2);

    // layer1: one group per CTA, high occupancy
    k_layer<3, 32, 4, 4, 16, 1, false><<<784, 256, sm1>>>(
        xt1, A1, nbr1, W1, b1, y1, stats + 0, stats + 32,
        nullptr, nullptr, nullptr, nullptr);
    // layer2: NQ=4 ct-split -> ~83 KB smem -> 2 CTAs/SM, RT=4 kept
    k_layer<32, 32, 4, 4, 16, 4, true><<<296, 256, sm2>>>(
        y1, A2, nbr2, W2, b2, y2, stats + 64, stats + 96,
        stats + 0, stats + 32, g1, be1);
    // layer3: NQ=8 ct-split -> ~110.5 KB smem -> 2 CTAs/SM, RT=4 kept
    k_layer<32, 64, 8, 4, 16, 8, true><<<296, 256, sm3>>>(
        y2, A2, nbr2, W3, b3, y3, stats + 128, stats + 192,
        stats + 64, stats + 96, g2, be2);

    k_pool<<<N3V / 16, 256>>>(y3, pidx, out, stats + 128, stats + 192, g3, be3);
}

// round 9
// speedup vs baseline: 1.9849x; 1.0377x over previous
#include <cuda_runtime.h>

#define BB 8
#define N1V 50176
#define N2V 12544
#define N3V 3136
#define CNT 100352          // BB*N2V
#define BN_EPS 1e-5f

typedef unsigned long long ull;

// ---------------- scratch ----------------
__device__ float d_xt1[N1V * 24];
__device__ float d_A1[N2V * 81];
__device__ float d_A2[N2V * 81];
__device__ float d_y1[N2V * 256];   // RAW outputs; BN fused into consumers
__device__ float d_y2[N2V * 256];
__device__ float d_y3[N2V * 512];
__device__ float d_stats[256];      // s1[32] q1[32] s2[32] q2[32] s3[64] q3[64]

// ---------------- f32x2 helpers ----------------
__device__ __forceinline__ ull pack2(float lo, float hi) {
    ull r; asm("mov.b64 %0, {%1, %2};" : "=l"(r) : "f"(lo), "f"(hi)); return r;
}
__device__ __forceinline__ void unpack2(ull v, float& lo, float& hi) {
    asm("mov.b64 {%0, %1}, %2;" : "=f"(lo), "=f"(hi) : "l"(v));
}
__device__ __forceinline__ ull ffma2(ull a, ull b, ull c) {
    ull d; asm("fma.rn.f32x2 %0, %1, %2, %3;" : "=l"(d) : "l"(a), "l"(b), "l"(c)); return d;
}

// ---------------- transpose x (8,3,N1) -> xt1[n][24]; block 0 zeros stats ----------------
__global__ void k_transpose(const float* __restrict__ x, float* __restrict__ xt,
                            float* __restrict__ stats) {
    int tid = threadIdx.x;
    if (blockIdx.x == 0) stats[tid] = 0.f;
    int n = blockIdx.x * 256 + tid;
    if (n >= N1V) return;
    float4 t4[6];
    float* t = (float*)t4;
#pragma unroll
    for (int bc = 0; bc < 24; ++bc) t[bc] = x[bc * N1V + n];
    float4* dst = (float4*)(xt + n * 24);
#pragma unroll
    for (int i = 0; i < 6; ++i) dst[i] = t4[i];
}

// ---------------- weight MLP (both offsets, one launch) ----------------
__global__ void __launch_bounds__(128) k_mlp2(const float* __restrict__ off1,
                      const float* __restrict__ off2,
                      const float* __restrict__ Wh, const float* __restrict__ bh,
                      const float* __restrict__ Wo, const float* __restrict__ bo,
                      float* __restrict__ A1, float* __restrict__ A2) {
    __shared__ float sWh[64], sbh[32], sWo[288], sbo[9];
    int tid = threadIdx.x;
    if (tid < 64) sWh[tid] = Wh[tid];
    if (tid < 32) sbh[tid] = bh[tid];
    for (int e = tid; e < 288; e += 128) sWo[e] = Wo[e];
    if (tid < 9) sbo[tid] = bo[tid];
    __syncthreads();
    int id = blockIdx.x * 128 + tid;
    const int T9 = N2V * 9;
    if (id >= 2 * T9) return;
    const float* off = (id < T9) ? off1 : off2;
    float* A = (id < T9) ? A1 : A2;
    int lid = (id < T9) ? id : id - T9;
    float2 o2 = ((const float2*)off)[lid];
    float h[32];
#pragma unroll
    for (int j = 0; j < 32; ++j)
        h[j] = fmaxf(0.f, fmaf(o2.x, sWh[j], fmaf(o2.y, sWh[32 + j], sbh[j])));
#pragma unroll
    for (int t = 0; t < 9; ++t) {
        float acc = sbo[t];
#pragma unroll
        for (int j = 0; j < 32; ++j) acc = fmaf(h[j], sWo[j * 9 + t], acc);
        A[lid * 9 + t] = acc;
    }
}

// ---------------- fused interp-conv layer, ct-split passes ----------------
// G stored TRANSPOSED: sm_G[ct_local * RS + row], row = pt*8+b, rows = 128.
// Stage C: column-tile per WARP (W loads warp-uniform -> smem broadcast),
// rows per lane (lane l -> rows 4l..4l+3, G read as one LDS.128).
template <int C, int O, int OT, int RT, int P, int NQ, int RS, bool BNIN>
__global__ void __launch_bounds__(256) k_layer(
    const float* __restrict__ xin, const float* __restrict__ A,
    const int* __restrict__ nbr, const float* __restrict__ Wg,
    const float* __restrict__ bias, float* __restrict__ yout,
    float* __restrict__ gSum, float* __restrict__ gSq,
    const float* __restrict__ pS, const float* __restrict__ pQ,
    const float* __restrict__ pG, const float* __restrict__ pB)
{
    constexpr int BCin = BB * C;
    constexpr int CT = C * 9;
    constexpr int CQ = C / NQ;         // channels per pass
    constexpr int CTQ = CQ * 9;        // ct per pass
    constexpr int ROWS = P * BB;       // 128
    constexpr int NG = N2V / P;        // 784
    constexpr int OTH = OT / 2;
    constexpr int BCq = BB * CQ;       // thread slots per point per pass
    constexpr int PPASS = 256 / BCq;   // points in flight per pass
    constexpr int NIT = P / PPASS;

    static_assert(ROWS / RT == 32 && O / OT == 8, "tiling");

    extern __shared__ float sm[];
    float* sm_Wt  = sm;                       // CT*O  [ct*O+o]
    float* sm_G   = sm_Wt + CT * O;           // CTQ*RS
    float* sm_a   = sm_G + CTQ * RS;          // P*108
    float* sm_bias= sm_a + P * 108;           // O
    float* sm_sum = sm_bias + O;              // O
    float* sm_sq  = sm_sum + O;               // O
    float* sm_sc  = sm_sq + O;                // C
    float* sm_sh  = sm_sc + C;                // C
    int*   sm_idx = (int*)(sm_sh + C);        // P*9

    const int tid = threadIdx.x;

    // one-time: weight transpose, bias, stats, BN coeffs
    for (int e = tid; e < CT * O; e += 256) {
        int ct = e / O, o = e - ct * O;
        sm_Wt[e] = Wg[o * CT + ct];
    }
    if (tid < O) { sm_bias[tid] = bias[tid]; sm_sum[tid] = 0.f; sm_sq[tid] = 0.f; }
    if (BNIN && tid < C) {
        float mean = pS[tid] * (1.f / CNT);
        float var  = pQ[tid] * (1.f / CNT) - mean * mean;
        float sc   = pG[tid] * rsqrtf(var + BN_EPS);
        sm_sc[tid] = sc;
        sm_sh[tid] = pB[tid] - mean * sc;
    }

    // stage-B decode (C==32 path)
    const int ptofs = tid / BCq;
    const int rem   = tid - ptofs * BCq;
    const int bB    = rem / CQ;
    const int ciB   = rem - bB * CQ;

    // stage-C decode: column tile per warp, rows per lane
    const int colt = tid >> 5;   // 0..7 (warp id) — warp-uniform
    const int lane = tid & 31;   // rows lane*4 .. lane*4+3

    float ssum[OT], ssq[OT];
#pragma unroll
    for (int j = 0; j < OT; ++j) { ssum[j] = 0.f; ssq[j] = 0.f; }

    for (int g = blockIdx.x; g < NG; g += gridDim.x) {
        const int n0 = g * P;
        if (tid < P * 9) sm_idx[tid] = nbr[n0 * 9 + tid];
        for (int e = tid; e < P * 81; e += 256) {
            int pt = e / 81, r = e - pt * 81, k = r / 9, t = r - k * 9;
            sm_a[pt * 108 + k * 12 + t] = A[(size_t)n0 * 81 + e];
        }
        __syncthreads();

        // persistent stage-C accumulators
        ull acc[RT][OTH];
#pragma unroll
        for (int i = 0; i < RT; ++i)
#pragma unroll
            for (int j = 0; j < OTH; ++j)
                acc[i][j] = pack2(sm_bias[colt * OT + 2 * j], sm_bias[colt * OT + 2 * j + 1]);

#pragma unroll 1
        for (int q = 0; q < NQ; ++q) {
            // ---- stage B pass q: compute G slice (transposed) ----
            if (C == 32) {
                const int cbase = q * CQ;
                const int colg = bB * C + cbase + ciB;     // b*C + c
                float scq = 1.f, shq = 0.f;
                if (BNIN) { scq = sm_sc[cbase + ciB]; shq = sm_sh[cbase + ciB]; }
#pragma unroll 1
                for (int it = 0; it < NIT; ++it) {
                    const int pt = it * PPASS + ptofs;
                    const int* ip = sm_idx + pt * 9;
                    float xr[9];
#pragma unroll
                    for (int k = 0; k < 9; ++k) xr[k] = xin[ip[k] * BCin + colg];
                    if (BNIN) {
#pragma unroll
                        for (int k = 0; k < 9; ++k) xr[k] = fmaxf(0.f, fmaf(xr[k], scq, shq));
                    }
                    const float* ap = sm_a + pt * 108;
                    ull ac01 = 0, ac23 = 0, ac45 = 0, ac67 = 0; float ac8 = 0.f;
#pragma unroll
                    for (int k = 0; k < 9; ++k) {
                        ull xx = pack2(xr[k], xr[k]);
                        const ulonglong2* a2 = (const ulonglong2*)(ap + k * 12);
                        ulonglong2 a03 = a2[0], a47 = a2[1];
                        ac01 = ffma2(xx, a03.x, ac01);
                        ac23 = ffma2(xx, a03.y, ac23);
                        ac45 = ffma2(xx, a47.x, ac45);
                        ac67 = ffma2(xx, a47.y, ac67);
                        ac8 = fmaf(xr[k], ap[k * 12 + 8], ac8);
                    }
                    float* gp = sm_G + (ciB * 9) * RS + pt * 8 + bB;
                    float v0,v1,v2,v3,v4,v5,v6,v7;
                    unpack2(ac01, v0, v1); unpack2(ac23, v2, v3);
                    unpack2(ac45, v4, v5); unpack2(ac67, v6, v7);
                    gp[0*RS]=v0; gp[1*RS]=v1; gp[2*RS]=v2; gp[3*RS]=v3;
                    gp[4*RS]=v4; gp[5*RS]=v5; gp[6*RS]=v6; gp[7*RS]=v7;
                    gp[8*RS]=ac8;
                }
            } else {  // C == 3, NQ == 1
#pragma unroll
                for (int it = tid; it < P * 24; it += 256) {
                    const int pt = it / 24, bc = it - pt * 24;
                    const int b = bc / 3, c = bc - b * 3;
                    const float* ap = sm_a + pt * 108;
                    const int* ip = sm_idx + pt * 9;
                    float xr[9];
#pragma unroll
                    for (int k = 0; k < 9; ++k) xr[k] = xin[ip[k] * BCin + bc];
                    ull ac01 = 0, ac23 = 0, ac45 = 0, ac67 = 0; float ac8 = 0.f;
#pragma unroll
                    for (int k = 0; k < 9; ++k) {
                        ull xx = pack2(xr[k], xr[k]);
                        const ulonglong2* a2 = (const ulonglong2*)(ap + k * 12);
                        ulonglong2 a03 = a2[0], a47 = a2[1];
                        ac01 = ffma2(xx, a03.x, ac01);
                        ac23 = ffma2(xx, a03.y, ac23);
                        ac45 = ffma2(xx, a47.x, ac45);
                        ac67 = ffma2(xx, a47.y, ac67);
                        ac8 = fmaf(xr[k], ap[k * 12 + 8], ac8);
                    }
                    float* gp = sm_G + (c * 9) * RS + pt * 8 + b;
                    float v0,v1,v2,v3,v4,v5,v6,v7;
                    unpack2(ac01, v0, v1); unpack2(ac23, v2, v3);
                    unpack2(ac45, v4, v5); unpack2(ac67, v6, v7);
                    gp[0*RS]=v0; gp[1*RS]=v1; gp[2*RS]=v2; gp[3*RS]=v3;
                    gp[4*RS]=v4; gp[5*RS]=v5; gp[6*RS]=v6; gp[7*RS]=v7;
                    gp[8*RS]=ac8;
                }
            }
            __syncthreads();   // G slice ready

            // ---- stage C pass q ----
            {
                const float* Wq = sm_Wt + (q * CTQ) * O + colt * OT;  // warp-uniform
                const float* Gq = sm_G + lane * RT;
#pragma unroll 4
                for (int ctl = 0; ctl < CTQ; ++ctl) {
                    ull w[OTH];
                    {
                        ulonglong2 wA = *(const ulonglong2*)(Wq + ctl * O);      // broadcast
                        w[0] = wA.x; w[1] = wA.y;
                        if (OTH > 2) {
                            ulonglong2 wB = *(const ulonglong2*)(Wq + ctl * O + 4);
                            w[2] = wB.x; w[3] = wB.y;
                        }
                    }
                    float4 gv = *(const float4*)(Gq + ctl * RS);
                    ull gg0 = pack2(gv.x, gv.x), gg1 = pack2(gv.y, gv.y);
                    ull gg2 = pack2(gv.z, gv.z), gg3 = pack2(gv.w, gv.w);
#pragma unroll
                    for (int j = 0; j < OTH; ++j) {
                        acc[0][j] = ffma2(gg0, w[j], acc[0][j]);
                        acc[1][j] = ffma2(gg1, w[j], acc[1][j]);
                        acc[2][j] = ffma2(gg2, w[j], acc[2][j]);
                        acc[3][j] = ffma2(gg3, w[j], acc[3][j]);
                    }
                }
            }
            __syncthreads();   // G slice consumed; safe to overwrite
        }

        // ---- write out + stats (registers only) ----
#pragma unroll
        for (int i = 0; i < RT; ++i) {
            int row = lane * RT + i, pt = row >> 3, b = row & 7;
            float* yp = yout + (size_t)(n0 + pt) * (BB * O) + b * O + colt * OT;
            float v[OT];
#pragma unroll
            for (int j = 0; j < OTH; ++j) unpack2(acc[i][j], v[2 * j], v[2 * j + 1]);
#pragma unroll
            for (int qv = 0; qv < OT / 4; ++qv)
                ((float4*)yp)[qv] = make_float4(v[4 * qv], v[4 * qv + 1], v[4 * qv + 2], v[4 * qv + 3]);
#pragma unroll
            for (int j = 0; j < OT; ++j) {
                ssum[j] += v[j];
                ssq[j] = fmaf(v[j], v[j], ssq[j]);
            }
        }
    }

    // stats merge: warp shuffle reduce (colt is warp-uniform), lane0 -> smem -> global
#pragma unroll
    for (int j = 0; j < OT; ++j) {
#pragma unroll
        for (int d = 16; d > 0; d >>= 1) {
            ssum[j] += __shfl_xor_sync(0xFFFFFFFFu, ssum[j], d);
            ssq[j]  += __shfl_xor_sync(0xFFFFFFFFu, ssq[j], d);
        }
    }
    if (lane == 0) {
#pragma unroll
        for (int j = 0; j < OT; ++j) {
            atomicAdd(sm_sum + colt * OT + j, ssum[j]);
            atomicAdd(sm_sq  + colt * OT + j, ssq[j]);
        }
    }
    __syncthreads();
    if (tid < O) {
        atomicAdd(gSum + tid, sm_sum[tid]);
        atomicAdd(gSq  + tid, sm_sq[tid]);
    }
}

// ---------------- max pool (+BN3+ReLU) + transpose to (8,64,N3) ----------------
__global__ void k_pool(const float* __restrict__ x3, const int* __restrict__ pidx,
                       float* __restrict__ out,
                       const float* __restrict__ gS, const float* __restrict__ gQ,
                       const float* __restrict__ gamma, const float* __restrict__ beta) {
    __shared__ float smp[16 * 513];
    int tid = threadIdx.x;
    int base = blockIdx.x * 16;
    int o = tid & 63;
    float mean = gS[o] * (1.f / CNT);
    float var  = gQ[o] * (1.f / CNT) - mean * mean;
    float sc   = gamma[o] * rsqrtf(var + BN_EPS);
    float sh   = beta[o] - mean * sc;
    bool pos = (sc >= 0.f);
    float init = pos ? -3.4e38f : 3.4e38f;
    for (int i = 0; i < 16; ++i) {
        int n3 = base + i;
        float m0 = init, m1 = init;
#pragma unroll
        for (int k = 0; k < 9; ++k) {
            const float* row = x3 + (size_t)pidx[n3 * 9 + k] * 512;
            float r0 = row[tid], r1 = row[tid + 256];
            if (pos) { m0 = fmaxf(m0, r0); m1 = fmaxf(m1, r1); }
            else     { m0 = fminf(m0, r0); m1 = fminf(m1, r1); }
        }
        smp[i * 513 + tid]       = fmaxf(0.f, fmaf(m0, sc, sh));
        smp[i * 513 + tid + 256] = fmaxf(0.f, fmaf(m1, sc, sh));
    }
    __syncthreads();
#pragma unroll
    for (int h = 0; h < 2; ++h) {
        int bc = tid + h * 256;
        float4 t4[4];
        float* t = (float*)t4;
#pragma unroll
        for (int i = 0; i < 16; ++i) t[i] = smp[i * 513 + bc];
        float4* dst = (float4*)(out + (size_t)bc * N3V + base);
#pragma unroll
        for (int q = 0; q < 4; ++q) dst[q] = t4[q];
    }
}

static constexpr size_t layer_smem(int C, int O, int NQ, int RS) {
    int CT = C * 9;
    int CTQ = (C / NQ) * 9;
    return (size_t)4 * (CT * O + CTQ * RS + 16 * 108 + 3 * O + 2 * C + 144);
}

extern "C" void kernel_launch(void* const* d_in, const int* in_sizes, int n_in,
                              void* d_out, int out_size) {
    const float* x    = (const float*)d_in[0];
    const int*   nbr1 = (const int*)d_in[1];
    const float* off1 = (const float*)d_in[2];
    const int*   nbr2 = (const int*)d_in[3];
    const float* off2 = (const float*)d_in[4];
    const int*   pidx = (const int*)d_in[5];
    const float* Wh   = (const float*)d_in[6];
    const float* bh   = (const float*)d_in[7];
    const float* Wo   = (const float*)d_in[8];
    const float* bo   = (const float*)d_in[9];
    const float* W1   = (const float*)d_in[10];
    const float* b1   = (const float*)d_in[11];
    const float* W2   = (const float*)d_in[12];
    const float* b2   = (const float*)d_in[13];
    const float* W3   = (const float*)d_in[14];
    const float* b3   = (const float*)d_in[15];
    const float* g1   = (const float*)d_in[16];
    const float* be1  = (const float*)d_in[17];
    const float* g2   = (const float*)d_in[18];
    const float* be2  = (const float*)d_in[19];
    const float* g3   = (const float*)d_in[20];
    const float* be3  = (const float*)d_in[21];
    float* out = (float*)d_out;

    float *xt1, *A1, *A2, *y1, *y2, *y3, *stats;
    cudaGetSymbolAddress((void**)&xt1, d_xt1);
    cudaGetSymbolAddress((void**)&A1, d_A1);
    cudaGetSymbolAddress((void**)&A2, d_A2);
    cudaGetSymbolAddress((void**)&y1, d_y1);
    cudaGetSymbolAddress((void**)&y2, d_y2);
    cudaGetSymbolAddress((void**)&y3, d_y3);
    cudaGetSymbolAddress((void**)&stats, d_stats);

    const size_t sm1 = layer_smem(3, 32, 1, 132);
    const size_t sm2 = layer_smem(32, 32, 4, 132);
    const size_t sm3 = layer_smem(32, 64, 8, 136);
    cudaFuncSetAttribute((const void*)k_layer<3, 32, 4, 4, 16, 1, 132, false>, cudaFuncAttributeMaxDynamicSharedMemorySize, (int)sm1);
    cudaFuncSetAttribute((const void*)k_layer<32, 32, 4, 4, 16, 4, 132, true>, cudaFuncAttributeMaxDynamicSharedMemorySize, (int)sm2);
    cudaFuncSetAttribute((const void*)k_layer<32, 64, 8, 4, 16, 8, 136, true>, cudaFuncAttributeMaxDynamicSharedMemorySize, (int)sm3);

    k_transpose<<<(N1V + 255) / 256, 256>>>(x, xt1, stats);
    k_mlp2<<<(2 * N2V * 9 + 127) / 128, 128>>>(off1, off2, Wh, bh, Wo, bo, A1, A2);

    // layer1: one group per CTA, high occupancy
    k_layer<3, 32, 4, 4, 16, 1, 132, false><<<784, 256, sm1>>>(
        xt1, A1, nbr1, W1, b1, y1, stats + 0, stats + 32,
        nullptr, nullptr, nullptr, nullptr);
    // layer2: NQ=4 ct-split, 2 CTAs/SM, warp-uniform W
    k_layer<32, 32, 4, 4, 16, 4, 132, true><<<296, 256, sm2>>>(
        y1, A2, nbr2, W2, b2, y2, stats + 64, stats + 96,
        stats + 0, stats + 32, g1, be1);
    // layer3: NQ=8 ct-split, RS=136 (conflict-free stage-B stores), 2 CTAs/SM
    k_layer<32, 64, 8, 4, 16, 8, 136, true><<<296, 256, sm3>>>(
        y2, A2, nbr2, W3, b3, y3, stats + 128, stats + 192,
        stats + 64, stats + 96, g2, be2);

    k_pool<<<N3V / 16, 256>>>(y3, pidx, out, stats + 128, stats + 192, g3, be3);
}